// round 4
// baseline (speedup 1.0000x reference)
#include <cuda_runtime.h>
#include <cuda_bf16.h>
#include <cstdint>

// out[n,R,C,co] = active[n,R/14,C/14] * (bias[co] + sum_{dy,dx,ci} x[n,R+dy,C+dx,ci]*k[dy,dx,ci,co])
// valid 3x3 conv 506x506 -> 504x504, gated per 14x14 tile by mask-block max > 0.5
//
// mma.sync bf16 formulation (tcgen05 unavailable: harness targets plain sm_103):
//   CTA tile = 8 out rows x 24 out cols (grid 21 x 63 x 8, exact -> no bounds checks)
//   warp w: 6 cols (3 m16 fragments, M = 2f+par column, 8 rows each)
//   K chunk = 16 ci; taps = per-lane ldmatrix address shifts; 3 bf16 hi/lo products

#define N_IMG 8
#define H_IN  506
#define W_IN  506
#define H_OUT 504
#define W_OUT 504
#define NBH   36
#define NBW   36

#define PIXB     144                 // bytes per pixel slot (128 data + 16 pad)
#define XROWP    27                  // padded pixel columns per x-row
#define XS_BYTES (10 * XROWP * PIXB) // 38880
#define WROWB    80                  // bytes per (tap,co) weight row (64 data + 16 pad)
#define WS_BYTES (2 * 9 * 32 * WROWB) // 46080
#define SMEM_BYTES (XS_BYTES + WS_BYTES)  // 84960

__device__ float g_active[N_IMG * NBH * NBW];

// ------------------------- helpers ------------------------------------------
__device__ __forceinline__ uint32_t smem_u32(const void* p) {
    uint32_t a;
    asm("{ .reg .u64 t; cvta.to.shared.u64 t, %1; cvt.u32.u64 %0, t; }"
        : "=r"(a) : "l"(p));
    return a;
}
__device__ __forceinline__ void sts16(uint32_t a, unsigned short v) {
    asm volatile("st.shared.b16 [%0], %1;" :: "r"(a), "h"(v) : "memory");
}
__device__ __forceinline__ void sts128(uint32_t a, uint32_t r0, uint32_t r1,
                                       uint32_t r2, uint32_t r3) {
    asm volatile("st.shared.v4.b32 [%0], {%1,%2,%3,%4};"
                 :: "r"(a), "r"(r0), "r"(r1), "r"(r2), "r"(r3) : "memory");
}
__device__ __forceinline__ void ldsm4(uint32_t* r, uint32_t addr) {
    asm volatile("ldmatrix.sync.aligned.m8n8.x4.shared.b16 {%0,%1,%2,%3}, [%4];"
                 : "=r"(r[0]), "=r"(r[1]), "=r"(r[2]), "=r"(r[3]) : "r"(addr));
}
__device__ __forceinline__ void mma4(float* d, const uint32_t* a, const uint32_t* b) {
    asm volatile(
        "mma.sync.aligned.m16n8k16.row.col.f32.bf16.bf16.f32 "
        "{%0,%1,%2,%3},{%4,%5,%6,%7},{%8,%9},{%0,%1,%2,%3};"
        : "+f"(d[0]), "+f"(d[1]), "+f"(d[2]), "+f"(d[3])
        : "r"(a[0]), "r"(a[1]), "r"(a[2]), "r"(a[3]), "r"(b[0]), "r"(b[1]));
}

// ---------------- kernel 1: mask block max -> active flag -------------------
__global__ void __launch_bounds__(256) mask_kernel(const float* __restrict__ mask) {
    __shared__ float red[256];
    int b = blockIdx.x;
    int n   = b / (NBH * NBW);
    int rem = b % (NBH * NBW);
    int bi = rem / NBW, bj = rem % NBW;
    int tid = threadIdx.x;
    int rr = tid >> 4, cc = tid & 15;
    red[tid] = mask[(n * H_IN + bi * 14 + rr) * W_IN + bj * 14 + cc];
    __syncthreads();
    #pragma unroll
    for (int s = 128; s > 0; s >>= 1) {
        if (tid < s) red[tid] = fmaxf(red[tid], red[tid + s]);
        __syncthreads();
    }
    if (tid == 0) g_active[b] = (red[0] > 0.5f) ? 1.0f : 0.0f;
}

// ---------------- kernel 2: conv via mma.sync bf16 --------------------------
__global__ void __launch_bounds__(128) conv_mma_kernel(
    const float* __restrict__ x,
    const float* __restrict__ kern,
    const float* __restrict__ bias,
    float* __restrict__ out)
{
    extern __shared__ char smem[];
    const uint32_t sm = smem_u32(smem);
    const uint32_t xs = sm;               // x: [10][27 pix pitch][144B: hi32ci|lo32ci|pad]
    const uint32_t ws = sm + XS_BYTES;    // w: [split][tap][co 32][80B: ci32 bf16|pad]

    const int tid = threadIdx.x;
    const int wid = tid >> 5;
    const int lid = tid & 31;
    const int n  = blockIdx.z;
    const int R0 = blockIdx.y * 8;
    const int C0 = blockIdx.x * 24;

    // ---- stage weights: kern[tap][ci][co] -> ws[split][tap][co][ci] ----
    for (int j = tid; j < 2304; j += 128) {
        float4 v = ((const float4*)kern)[j];       // 4 consecutive co
        int co4 = (j & 7) * 4;
        int ci  = (j >> 3) & 31;
        int tap = j >> 8;
        float f[4] = {v.x, v.y, v.z, v.w};
        #pragma unroll
        for (int e = 0; e < 4; e++) {
            __nv_bfloat16 h = __float2bfloat16_rn(f[e]);
            __nv_bfloat16 l = __float2bfloat16_rn(f[e] - __bfloat162float(h));
            uint32_t a0 = ws + (uint32_t)((tap * 32 + co4 + e) * WROWB + ci * 2);
            sts16(a0, __bfloat16_as_ushort(h));
            sts16(a0 + 9 * 32 * WROWB, __bfloat16_as_ushort(l));
        }
    }

    // ---- stage x tile: 10 rows x 26 cols x 32 ci, hi/lo bf16 ----
    for (int j = tid; j < 1040; j += 128) {
        int p = j >> 2, oct = j & 3;               // pixel, octet of 8 ci
        int ir = p / 26, ic = p - ir * 26;
        const float4* gp = (const float4*)
            (x + (((size_t)n * H_IN + R0 + ir) * W_IN + C0 + ic) * 32 + oct * 8);
        float4 va = gp[0], vb = gp[1];
        float fv[8] = {va.x, va.y, va.z, va.w, vb.x, vb.y, vb.z, vb.w};
        uint32_t hi[4], lo[4];
        #pragma unroll
        for (int q = 0; q < 4; q++) {
            float f0 = fv[2 * q], f1 = fv[2 * q + 1];
            __nv_bfloat162 h  = __floats2bfloat162_rn(f0, f1);
            float r0 = f0 - __bfloat162float(h.x);
            float r1 = f1 - __bfloat162float(h.y);
            __nv_bfloat162 lw = __floats2bfloat162_rn(r0, r1);
            hi[q] = *reinterpret_cast<uint32_t*>(&h);
            lo[q] = *reinterpret_cast<uint32_t*>(&lw);
        }
        uint32_t a = xs + (uint32_t)((ir * XROWP + ic) * PIXB + oct * 16);
        sts128(a,      hi[0], hi[1], hi[2], hi[3]);
        sts128(a + 64, lo[0], lo[1], lo[2], lo[3]);
    }
    __syncthreads();

    // ---- main: 3 split-products x 9 taps x 2 ci-chunks ----
    const int cc0 = wid * 6;
    // A lane address: M0 lanes0-7 rows(rr)=l&7 col cc0; M1 lanes8-15 col+1; M2/M3 k+16B
    const uint32_t baseA = xs + (uint32_t)
        ((((lid & 7) * XROWP) + cc0 + ((lid >> 3) & 1)) * PIXB + (lid >> 4) * 16);
    // B lane address: co = (l&7) + (l>>4)*8 ; k half via (l>>3)&1
    const uint32_t baseB = ws + (uint32_t)
        ((((lid & 7) + ((lid >> 4) << 3)) * WROWB) + ((lid >> 3) & 1) * 16);

    float d[3][4][4];
    #pragma unroll
    for (int f = 0; f < 3; f++)
        #pragma unroll
        for (int nb = 0; nb < 4; nb++)
            #pragma unroll
            for (int e = 0; e < 4; e++) d[f][nb][e] = 0.0f;

    #pragma unroll
    for (int s = 0; s < 3; s++) {                  // AhBh, AhBl, AlBh
        const int sA = (s == 2), sB = (s == 1);
        #pragma unroll
        for (int tap = 0; tap < 9; tap++) {
            const int dy = tap / 3, dx = tap % 3;
            const uint32_t aoff = baseA + (dy * XROWP + dx) * PIXB + sA * 64;
            const uint32_t boff = baseB + (sB * 9 + tap) * (32 * WROWB);
            #pragma unroll
            for (int h = 0; h < 2; h++) {
                uint32_t A0[4], A1[4], A2[4], B0[4], B1[4];
                ldsm4(B0, boff + h * 32);              // co 0..15
                ldsm4(B1, boff + h * 32 + 16 * WROWB); // co 16..31
                ldsm4(A0, aoff + h * 32);
                ldsm4(A1, aoff + h * 32 + 2 * PIXB);
                ldsm4(A2, aoff + h * 32 + 4 * PIXB);
                mma4(d[0][0], A0, B0);  mma4(d[0][1], A0, B0 + 2);
                mma4(d[0][2], A0, B1);  mma4(d[0][3], A0, B1 + 2);
                mma4(d[1][0], A1, B0);  mma4(d[1][1], A1, B0 + 2);
                mma4(d[1][2], A1, B1);  mma4(d[1][3], A1, B1 + 2);
                mma4(d[2][0], A2, B0);  mma4(d[2][1], A2, B0 + 2);
                mma4(d[2][2], A2, B1);  mma4(d[2][3], A2, B1 + 2);
            }
        }
    }

    // ---- epilogue ----
    const int rr = lid >> 2;
    const int j2 = (lid & 3) * 2;
    const int R = R0 + rr;
    const float* act_row = g_active + (n * NBH + R / 14) * NBW;
    float2 bv[4];
    #pragma unroll
    for (int nb = 0; nb < 4; nb++)
        bv[nb] = *(const float2*)(bias + nb * 8 + j2);

    #pragma unroll
    for (int f = 0; f < 3; f++) {
        #pragma unroll
        for (int par = 0; par < 2; par++) {
            int C = C0 + cc0 + 2 * f + par;
            float fg = act_row[C / 14];
            float* op = out + (((size_t)n * H_OUT + R) * W_OUT + C) * 32 + j2;
            #pragma unroll
            for (int nb = 0; nb < 4; nb++) {
                float2 v;
                v.x = (d[f][nb][par * 2 + 0] + bv[nb].x) * fg;
                v.y = (d[f][nb][par * 2 + 1] + bv[nb].y) * fg;
                *(float2*)(op + nb * 8) = v;
            }
        }
    }
}

// ---------------------------------------------------------------------------
extern "C" void kernel_launch(void* const* d_in, const int* in_sizes, int n_in,
                              void* d_out, int out_size)
{
    const float* x    = (const float*)d_in[0];
    const float* mask = (const float*)d_in[1];
    const float* kern = (const float*)d_in[2];
    const float* bias = (const float*)d_in[3];
    float* out = (float*)d_out;
    (void)in_sizes; (void)n_in; (void)out_size;

    cudaFuncSetAttribute(conv_mma_kernel,
                         cudaFuncAttributeMaxDynamicSharedMemorySize, SMEM_BYTES);

    mask_kernel<<<N_IMG * NBH * NBW, 256>>>(mask);

    dim3 grid(21, 63, N_IMG);        // 21*24 = 504, 63*8 = 504 (exact)
    conv_mma_kernel<<<grid, 128, SMEM_BYTES>>>(x, kern, bias, out);
}

// round 5
// speedup vs baseline: 2.1010x; 2.1010x over previous
#include <cuda_runtime.h>
#include <cuda_bf16.h>
#include <cstdint>

// out[n,R,C,co] = active[n,R/14,C/14] * (bias[co] + sum_{dy,dx,ci} x[n,R+dy,C+dx,ci]*k[dy,dx,ci,co])
// valid 3x3 conv 506x506 -> 504x504, gated per 14x14 tile by mask-block max > 0.5
//
// mma.sync bf16 (fp32 = hi+lo bf16, 3 products AhBh+AhBl+AlBh):
//   persistent CTAs, tile 16x16 outputs, 4 warps, warp = 4 cols x 16 rows (M=64) x 32 co
//   taps are per-lane ldmatrix address shifts

#define N_IMG 8
#define H_IN  506
#define W_IN  506
#define H_OUT 504
#define W_OUT 504
#define NBH   36
#define NBW   36

#define TILES_PER_IMG 1024           // 32 x 32 tiles of 16x16
#define N_TILES (N_IMG * TILES_PER_IMG)
#define GRID_CONV 296

#define XROWP 19                     // pixel-column pitch (19*144/16 = 171 ≡ 3 mod 8)
#define PIXB  144                    // 64B hi(ci0-31) + 64B lo + 16 pad
#define XS_BYTES (18 * XROWP * PIXB) // 49248
#define WROWB 80                     // 64B ci + 16 pad  (80/16 = 5, odd -> conflict-free)
#define WSPLIT (9 * 32 * WROWB)      // 23040
#define WS_BYTES (2 * WSPLIT)        // 46080
#define SMEM_BYTES (XS_BYTES + WS_BYTES)   // 95328

__device__ float g_active[N_IMG * NBH * NBW];

// ------------------------- helpers ------------------------------------------
__device__ __forceinline__ uint32_t smem_u32(const void* p) {
    uint32_t a;
    asm("{ .reg .u64 t; cvta.to.shared.u64 t, %1; cvt.u32.u64 %0, t; }"
        : "=r"(a) : "l"(p));
    return a;
}
__device__ __forceinline__ void sts64(uint32_t a, uint64_t v) {
    asm volatile("st.shared.b64 [%0], %1;" :: "r"(a), "l"(v) : "memory");
}
__device__ __forceinline__ void sts128(uint32_t a, uint32_t r0, uint32_t r1,
                                       uint32_t r2, uint32_t r3) {
    asm volatile("st.shared.v4.b32 [%0], {%1,%2,%3,%4};"
                 :: "r"(a), "r"(r0), "r"(r1), "r"(r2), "r"(r3) : "memory");
}
__device__ __forceinline__ void ldsm4(uint32_t* r, uint32_t addr) {
    asm volatile("ldmatrix.sync.aligned.m8n8.x4.shared.b16 {%0,%1,%2,%3}, [%4];"
                 : "=r"(r[0]), "=r"(r[1]), "=r"(r[2]), "=r"(r[3]) : "r"(addr));
}
__device__ __forceinline__ void mma4(float* d, const uint32_t* a, const uint32_t* b) {
    asm volatile(
        "mma.sync.aligned.m16n8k16.row.col.f32.bf16.bf16.f32 "
        "{%0,%1,%2,%3},{%4,%5,%6,%7},{%8,%9},{%0,%1,%2,%3};"
        : "+f"(d[0]), "+f"(d[1]), "+f"(d[2]), "+f"(d[3])
        : "r"(a[0]), "r"(a[1]), "r"(a[2]), "r"(a[3]), "r"(b[0]), "r"(b[1]));
}
__device__ __forceinline__ unsigned short bf_hi(float f) {
    return __bfloat16_as_ushort(__float2bfloat16_rn(f));
}

// ---------------- kernel 1: mask block max -> active flag -------------------
__global__ void __launch_bounds__(256) mask_kernel(const float* __restrict__ mask) {
    __shared__ float red[256];
    int b = blockIdx.x;
    int n   = b / (NBH * NBW);
    int rem = b % (NBH * NBW);
    int bi = rem / NBW, bj = rem % NBW;
    int tid = threadIdx.x;
    int rr = tid >> 4, cc = tid & 15;
    red[tid] = mask[(n * H_IN + bi * 14 + rr) * W_IN + bj * 14 + cc];
    __syncthreads();
    #pragma unroll
    for (int s = 128; s > 0; s >>= 1) {
        if (tid < s) red[tid] = fmaxf(red[tid], red[tid + s]);
        __syncthreads();
    }
    if (tid == 0) g_active[b] = (red[0] > 0.5f) ? 1.0f : 0.0f;
}

// ---------------- kernel 2: persistent conv via mma.sync --------------------
__global__ void __launch_bounds__(128, 3) conv_mma_kernel(
    const float* __restrict__ x,
    const float* __restrict__ kern,
    const float* __restrict__ bias,
    float* __restrict__ out)
{
    extern __shared__ char smem[];
    const uint32_t xs = smem_u32(smem);
    const uint32_t ws = xs + XS_BYTES;
    const int tid = threadIdx.x;
    const int wid = tid >> 5;
    const int lid = tid & 31;

    // ---- stage weights once: kern[tap][ci][co] -> ws[split][tap][co][ci bf16] ----
    for (int j = tid; j < 2304; j += 128) {
        int ciq = j & 7;                // quad of ci
        int co  = (j >> 3) & 31;
        int tap = j >> 8;
        int ci  = ciq * 4;
        const float* kp = kern + (tap * 32 + ci) * 32 + co;
        float f0 = kp[0], f1 = kp[32], f2 = kp[64], f3 = kp[96];
        unsigned short h0 = bf_hi(f0), h1 = bf_hi(f1), h2 = bf_hi(f2), h3 = bf_hi(f3);
        unsigned short l0 = bf_hi(f0 - __bfloat162float(__ushort_as_bfloat16(h0)));
        unsigned short l1 = bf_hi(f1 - __bfloat162float(__ushort_as_bfloat16(h1)));
        unsigned short l2 = bf_hi(f2 - __bfloat162float(__ushort_as_bfloat16(h2)));
        unsigned short l3 = bf_hi(f3 - __bfloat162float(__ushort_as_bfloat16(h3)));
        uint64_t hi64 = (uint64_t)h0 | ((uint64_t)h1 << 16)
                      | ((uint64_t)h2 << 32) | ((uint64_t)h3 << 48);
        uint64_t lo64 = (uint64_t)l0 | ((uint64_t)l1 << 16)
                      | ((uint64_t)l2 << 32) | ((uint64_t)l3 << 48);
        uint32_t a = ws + (uint32_t)((tap * 32 + co) * WROWB + ciq * 8);
        sts64(a, hi64);
        sts64(a + WSPLIT, lo64);
    }

    // per-lane ldmatrix base addresses
    const int cw = wid * 4;
    const uint32_t baseA = xs + (uint32_t)
        (((((lid & 7) + 8 * ((lid >> 3) & 1)) * XROWP) + cw) * PIXB + (lid >> 4) * 16);
    const uint32_t baseB = ws + (uint32_t)
        ((((lid & 7) + ((lid >> 4) << 3)) * WROWB) + ((lid >> 3) & 1) * 16);

    for (int t = blockIdx.x; t < N_TILES; t += GRID_CONV) {
        const int n   = t >> 10;
        const int rem = t & 1023;
        const int R0 = (rem >> 5) * 16;
        const int C0 = (rem & 31) * 16;

        __syncthreads();   // previous iteration's readers done before overwrite

        // ---- stage x: 18x18 pixels x 32 ci, hi/lo bf16 ----
        for (int j = tid; j < 1296; j += 128) {
            int oct = j & 3;
            int p   = j >> 2;
            int ir = p / 18, ic = p - ir * 18;
            int gr = R0 + ir; if (gr > H_IN - 1) gr = H_IN - 1;
            int gc = C0 + ic; if (gc > W_IN - 1) gc = W_IN - 1;
            const float4* gp = (const float4*)
                (x + (((size_t)n * H_IN + gr) * W_IN + gc) * 32 + oct * 8);
            float4 va = gp[0], vb = gp[1];
            float fv[8] = {va.x, va.y, va.z, va.w, vb.x, vb.y, vb.z, vb.w};
            uint32_t hi[4], lo[4];
            #pragma unroll
            for (int q = 0; q < 4; q++) {
                float f0 = fv[2 * q], f1 = fv[2 * q + 1];
                __nv_bfloat162 h = __floats2bfloat162_rn(f0, f1);
                float r0 = f0 - __bfloat162float(h.x);
                float r1 = f1 - __bfloat162float(h.y);
                __nv_bfloat162 lw = __floats2bfloat162_rn(r0, r1);
                hi[q] = *reinterpret_cast<uint32_t*>(&h);
                lo[q] = *reinterpret_cast<uint32_t*>(&lw);
            }
            uint32_t a = xs + (uint32_t)((ir * XROWP + ic) * PIXB + oct * 16);
            sts128(a,      hi[0], hi[1], hi[2], hi[3]);
            sts128(a + 64, lo[0], lo[1], lo[2], lo[3]);
        }
        __syncthreads();

        // ---- main loop: 9 taps x 2 k-chunks ----
        float d[4][4][4];
        #pragma unroll
        for (int f = 0; f < 4; f++)
            #pragma unroll
            for (int nb = 0; nb < 4; nb++)
                #pragma unroll
                for (int e = 0; e < 4; e++) d[f][nb][e] = 0.0f;

        #pragma unroll 1
        for (int dy = 0; dy < 3; dy++) {
            #pragma unroll 1
            for (int dx = 0; dx < 3; dx++) {
                const uint32_t ao = baseA + (uint32_t)((dy * XROWP + dx) * PIXB);
                const uint32_t bo = baseB + (uint32_t)((dy * 3 + dx) * (32 * WROWB));
                #pragma unroll
                for (int h = 0; h < 2; h++) {
                    uint32_t Ah[16], Al[16], Bh[8], Bl[8];
                    const uint32_t hb = h * 32;
                    ldsm4(Bh,     bo + hb);
                    ldsm4(Bh + 4, bo + hb + 16 * WROWB);
                    ldsm4(Bl,     bo + hb + WSPLIT);
                    ldsm4(Bl + 4, bo + hb + WSPLIT + 16 * WROWB);
                    #pragma unroll
                    for (int f = 0; f < 4; f++) ldsm4(Ah + 4 * f, ao + hb + f * PIXB);
                    #pragma unroll
                    for (int f = 0; f < 4; f++) ldsm4(Al + 4 * f, ao + hb + 64 + f * PIXB);
                    #pragma unroll
                    for (int f = 0; f < 4; f++)
                        #pragma unroll
                        for (int nb = 0; nb < 4; nb++)
                            mma4(d[f][nb], Ah + 4 * f, Bh + 2 * nb);
                    #pragma unroll
                    for (int f = 0; f < 4; f++)
                        #pragma unroll
                        for (int nb = 0; nb < 4; nb++)
                            mma4(d[f][nb], Ah + 4 * f, Bl + 2 * nb);
                    #pragma unroll
                    for (int f = 0; f < 4; f++)
                        #pragma unroll
                        for (int nb = 0; nb < 4; nb++)
                            mma4(d[f][nb], Al + 4 * f, Bh + 2 * nb);
                }
            }
        }

        // ---- epilogue ----
        const int r0 = lid >> 2;
        const int n2 = (lid & 3) * 2;
        const int R1 = R0 + r0;            // always < 504
        const int R2 = R1 + 8;
        const bool r2ok = (R2 < H_OUT);
        const int R2c = r2ok ? R2 : H_OUT - 1;
        const float* act1 = g_active + (n * NBH + R1 / 14) * NBW;
        const float* act2 = g_active + (n * NBH + R2c / 14) * NBW;
        float2 bv[4];
        #pragma unroll
        for (int nb = 0; nb < 4; nb++)
            bv[nb] = *(const float2*)(bias + nb * 8 + n2);

        #pragma unroll
        for (int f = 0; f < 4; f++) {
            const int C = C0 + cw + f;
            if (C < W_OUT) {
                const int cb = C / 14;
                float fg1 = act1[cb];
                float* o1 = out + (((size_t)n * H_OUT + R1) * W_OUT + C) * 32 + n2;
                #pragma unroll
                for (int nb = 0; nb < 4; nb++) {
                    float2 v;
                    v.x = (d[f][nb][0] + bv[nb].x) * fg1;
                    v.y = (d[f][nb][1] + bv[nb].y) * fg1;
                    *(float2*)(o1 + nb * 8) = v;
                }
                if (r2ok) {
                    float fg2 = act2[cb];
                    float* o2 = out + (((size_t)n * H_OUT + R2) * W_OUT + C) * 32 + n2;
                    #pragma unroll
                    for (int nb = 0; nb < 4; nb++) {
                        float2 v;
                        v.x = (d[f][nb][2] + bv[nb].x) * fg2;
                        v.y = (d[f][nb][3] + bv[nb].y) * fg2;
                        *(float2*)(o2 + nb * 8) = v;
                    }
                }
            }
        }
    }
}

// ---------------------------------------------------------------------------
extern "C" void kernel_launch(void* const* d_in, const int* in_sizes, int n_in,
                              void* d_out, int out_size)
{
    const float* x    = (const float*)d_in[0];
    const float* mask = (const float*)d_in[1];
    const float* kern = (const float*)d_in[2];
    const float* bias = (const float*)d_in[3];
    float* out = (float*)d_out;
    (void)in_sizes; (void)n_in; (void)out_size;

    cudaFuncSetAttribute(conv_mma_kernel,
                         cudaFuncAttributeMaxDynamicSharedMemorySize, SMEM_BYTES);

    mask_kernel<<<N_IMG * NBH * NBW, 256>>>(mask);
    conv_mma_kernel<<<GRID_CONV, 128, SMEM_BYTES>>>(x, kern, bias, out);
}